// round 6
// baseline (speedup 1.0000x reference)
#include <cuda_runtime.h>
#include <cuda_fp16.h>

// V2STransformer: volume-to-slice affine resample with trilinear interpolation.
// vol: [B,H,W,D] f32 (B=8,H=160,W=160,D=96), trf: [B,S,12] (S=64), out: [B,H,W,S].
//
// Pass 1: transpose+pack, one block per (b, padded-h) plane:
//         pair[b][h][d][w] = half2( v, v[w+1 clamped] - v ), dims [B][H+1][D+1][W]
//         float4 global reads, half smem tile (31.4 KB), conflict-free emit.
// Pass 2: lanes = w; 4 half2 gathers per sample at immediate offsets;
//         y-lerp is a single FMA (delta form).

#define BB 8
#define HH 160
#define WW 160
#define DD 96
#define SS 64
#define ST_RATIO 1.5f
#define HP (HH + 1)   // 161 padded h-planes per batch
#define DP (DD + 1)   // 97 padded d-rows per plane

// Packed pair volume: [b][h(161)][d(97)][w(160)] half2. 80 MB.
__device__ __half2 vol_p_buf[(size_t)BB * HP * DP * WW];

// ---------------------------------------------------------------------------
// Pass 1: per-(b,h) full-plane transpose [W, D] -> [D, W] with delta pairing.
// Block = 512 threads, one padded h-plane each.
// ---------------------------------------------------------------------------
__global__ __launch_bounds__(512)
void v2s_pack_kernel(const float* __restrict__ vol) {
    // smem: halves, row stride 98 (49 half2) per w-row -> LDS bank stride 49
    // (odd, coprime with 32) on the emit side: conflict-free.
    __shared__ __half2 tile2[WW * 49];               // 160*49*4B = 31.4 KB

    const int bh = blockIdx.x;                       // b*HP + h_padded
    const int b  = bh / HP;
    const int hh = bh - b * HP;                      // 0..160
    const int hs = min(hh, HH - 1);                  // plane 160 = copy of 159
    const int tid = threadIdx.x;

    const float4* __restrict__ src4 =
        reinterpret_cast<const float4*>(vol + ((size_t)b * HH + hs) * WW * DD);
    __half2* __restrict__ dst = vol_p_buf + (size_t)bh * DP * WW;   // [d][w]

    // Load plane: 160 w-rows x 24 float4 (96 d). Coalesced, high MLP.
    #pragma unroll
    for (int it = 0; it < 8; it++) {
        const int idx = tid + it * 512;              // < 3840 except last chunk
        if (idx < WW * (DD / 4)) {
            const int w  = idx / (DD / 4);
            const int d4 = idx - w * (DD / 4);
            const float4 v = src4[idx];
            __half2* row = tile2 + w * 49 + d4 * 2;
            row[0] = __floats2half2_rn(v.x, v.y);
            row[1] = __floats2half2_rn(v.z, v.w);
        }
    }
    __syncthreads();

    // Emit (v, v[w+1]-v) pairs: 97 padded d-rows x 160 w. Lanes along w:
    // LDS.16 bank stride 49 -> conflict-free; stores coalesced.
    const __half* th = reinterpret_cast<const __half*>(tile2);
    for (int idx = tid; idx < DP * WW; idx += 512) {
        const int d  = idx / WW;
        const int w  = idx - d * WW;
        const int ds = min(d, DD - 1);               // d row 96 = copy of 95
        const int wn = min(w + 1, WW - 1);
        const float a = __half2float(th[w  * 98 + ds]);
        const float c = __half2float(th[wn * 98 + ds]);
        dst[(size_t)d * WW + w] = __floats2half2_rn(a, c - a);
    }
}

// ---------------------------------------------------------------------------
// Pass 2: main resample. Block = (32 w-lanes, 8), covers (1 h, 32 w, 64 s).
// ---------------------------------------------------------------------------
__global__ __launch_bounds__(256, 4)
void v2s_main_kernel(const float* __restrict__ trf,
                     float* __restrict__ out) {
    // Per-s fused affine partials: coord_r = fmaf(coef_r, fj, P_r).
    __shared__ float Pre[SS][8];             // [s][{cx,Px,cy,Py,cz,Pz,_,_}]
    __shared__ float tile[32][SS + 1];       // [w_local][s]

    const int b  = blockIdx.z;
    const int h  = blockIdx.y;
    const int w0 = blockIdx.x * 32;
    const int tx = threadIdx.x;              // w lane: 0..31
    const int ty = threadIdx.y;              // 0..7
    const int tid = ty * 32 + tx;

    const float fi = (float)h;

    // 64 s * 3 axes = 192 precompute items.
    for (int it = tid; it < SS * 3; it += 256) {
        const int s = it / 3;
        const int r = it - s * 3;
        const float* t = trf + ((size_t)b * SS + s) * 12 + r * 4;
        const float a0 = t[0] + (r == 0 ? 1.0f : 0.0f);
        const float a1 = t[1] + (r == 1 ? 1.0f : 0.0f);
        const float a2 = t[2] + (r == 2 ? 1.0f : 0.0f);
        const float a3 = t[3];
        const float fz = (float)s * ST_RATIO;
        Pre[s][r * 2]     = a1;
        Pre[s][r * 2 + 1] = fmaf(a0, fi, fmaf(a2, fz, a3));
    }
    __syncthreads();

    const __half2* __restrict__ vp = vol_p_buf + (size_t)b * (HP * DP * WW);
    const float fj = (float)(w0 + tx);

    #pragma unroll
    for (int k = 0; k < 8; k++) {
        const int s = ty * 8 + k;            // all lanes in warp share s
        const float4 q  = *reinterpret_cast<const float4*>(&Pre[s][0]);
        const float2 q2 = *reinterpret_cast<const float2*>(&Pre[s][4]);

        float x = fmaf(q.x,  fj, q.y);
        float y = fmaf(q.z,  fj, q.w);
        float z = fmaf(q2.x, fj, q2.y);

        x = fminf(fmaxf(x, 0.0f), (float)(HH - 1));
        y = fminf(fmaxf(y, 0.0f), (float)(WW - 1));
        z = fminf(fmaxf(z, 0.0f), (float)(DD - 1));

        const float xf = floorf(x), yf = floorf(y), zf = floorf(z);
        const float dx = x - xf, dy = y - yf, dz = z - zf;
        const int x0 = (int)xf, y0 = (int)yf, z0 = (int)zf;

        // padded layout: idx = (x*DP + z)*W + y ; neighbors at imm offsets
        const __half2* p = vp + ((x0 * DP + z0) * WW + y0);
        const float2 f00 = __half22float2(__ldg(p));                 // (x0,z0)
        const float2 f01 = __half22float2(__ldg(p + WW));            // (x0,z1)
        const float2 f10 = __half22float2(__ldg(p + DP * WW));       // (x1,z0)
        const float2 f11 = __half22float2(__ldg(p + DP * WW + WW));  // (x1,z1)

        // y-lerp = single FMA (delta form), then z, then x
        const float c00 = fmaf(dy, f00.y, f00.x);
        const float c01 = fmaf(dy, f01.y, f01.x);
        const float c10 = fmaf(dy, f10.y, f10.x);
        const float c11 = fmaf(dy, f11.y, f11.x);
        const float c0  = fmaf(dz, c01 - c00, c00);
        const float c1  = fmaf(dz, c11 - c10, c10);
        const float r   = fmaf(dx, c1 - c0, c0);

        tile[tx][s] = r;
    }
    __syncthreads();

    // Coalesced write: consecutive tids -> consecutive s.
    float* __restrict__ ob = out + (((size_t)b * HH + h) * WW + w0) * SS;
    #pragma unroll
    for (int idx = tid; idx < 32 * SS; idx += 256) {
        const int wl = idx >> 6;
        const int s  = idx & 63;
        ob[(size_t)wl * SS + s] = tile[wl][s];
    }
}

extern "C" void kernel_launch(void* const* d_in, const int* in_sizes, int n_in,
                              void* d_out, int out_size) {
    const float* vol = (const float*)d_in[0];
    const float* trf = (const float*)d_in[1];
    float* out = (float*)d_out;

    {
        dim3 block(512, 1, 1);
        dim3 grid(BB * HP, 1, 1);               // 1288 blocks, one plane each
        v2s_pack_kernel<<<grid, block>>>(vol);
    }
    {
        dim3 block(32, 8, 1);
        dim3 grid(WW / 32, HH, BB);             // (5, 160, 8)
        v2s_main_kernel<<<grid, block>>>(trf, out);
    }
}

// round 7
// speedup vs baseline: 1.1224x; 1.1224x over previous
#include <cuda_runtime.h>
#include <cuda_fp16.h>

// V2STransformer: volume-to-slice affine resample with trilinear interpolation.
// vol: [B,H,W,D] f32 (B=8,H=160,W=160,D=96), trf: [B,S,12] (S=64), out: [B,H,W,S].
//
// Pass 1: 32x32-tile transpose+pack (R2-proven shape, fully unrolled, no
//         division): pair[b][h][d][w] = half2(v, v[w+1 clamped]-v),
//         dims [B][H+1][D+1][W] (h=H plane dups h=H-1, d=D row dups d=D-1).
// Pass 2: lanes = w; 4 half2 gathers per sample at immediate offsets;
//         y-lerp is a single FMA (delta form). Unchanged from R5/R6.
// Dummy no-op launches shift ncu's -s 5 window onto the pack kernel.

#define BB 8
#define HH 160
#define WW 160
#define DD 96
#define SS 64
#define ST_RATIO 1.5f
#define HP (HH + 1)   // 161 padded h-planes per batch
#define DP (DD + 1)   // 97 padded d-rows per plane

// Packed pair volume: [b][h(161)][d(97)][w(160)] half2. 80 MB.
__device__ __half2 vol_p_buf[(size_t)BB * HP * DP * WW];

__global__ void v2s_dummy_kernel() {}

// ---------------------------------------------------------------------------
// Pass 1: 32x32 tiles, block (32,8). grid = (D/32, W/32, B*HP).
// ---------------------------------------------------------------------------
__global__ __launch_bounds__(256)
void v2s_pack_kernel(const float* __restrict__ vol) {
    __shared__ float tile[33][33];          // [w_local][d_local]

    const int d0 = blockIdx.x * 32;         // 0, 32, 64
    const int w0 = blockIdx.y * 32;         // 0..128
    const int bh = blockIdx.z;              // b*HP + h_padded
    const int b  = bh / HP;
    const int hh = bh - b * HP;             // 0..160
    const int hs = min(hh, HH - 1);         // plane 160 = copy of 159
    const int tx = threadIdx.x;             // 32
    const int ty = threadIdx.y;             // 8

    const float* __restrict__ src = vol + ((size_t)b * HH + hs) * WW * DD;
    __half2* __restrict__ dst = vol_p_buf + (size_t)bh * DP * WW;   // [d][w]

    // Load 32 w-rows x 32 d, coalesced along d. 4 independent LDGs/thread.
    #pragma unroll
    for (int i = 0; i < 32; i += 8)
        tile[ty + i][tx] = src[(size_t)(w0 + ty + i) * DD + d0 + tx];
    // Extra boundary row (w0+32, clamped) for the pairing neighbor.
    if (ty == 0) {
        const int wsrc = min(w0 + 32, WW - 1);
        tile[32][tx] = src[(size_t)wsrc * DD + d0 + tx];
    }
    __syncthreads();

    // Emit (v, v[w+1]-v): lanes along w (stride-33 LDS, conflict-free),
    // coalesced 4B stores. 4 unrolled iterations, constant index math.
    #pragma unroll
    for (int i = 0; i < 32; i += 8) {
        const int dl = ty + i;
        const float a = tile[tx][dl];
        const float c = tile[tx + 1][dl];
        dst[(size_t)(d0 + dl) * WW + w0 + tx] = __floats2half2_rn(a, c - a);
    }
    // d-pad row 96 (copy of d=95), emitted by the d0==64 blocks, warp 7.
    if (d0 == 64 && ty == 7) {
        const float a = tile[tx][31];
        const float c = tile[tx + 1][31];
        dst[(size_t)96 * WW + w0 + tx] = __floats2half2_rn(a, c - a);
    }
}

// ---------------------------------------------------------------------------
// Pass 2: main resample. Block = (32 w-lanes, 8), covers (1 h, 32 w, 64 s).
// ---------------------------------------------------------------------------
__global__ __launch_bounds__(256, 4)
void v2s_main_kernel(const float* __restrict__ trf,
                     float* __restrict__ out) {
    // Per-s fused affine partials: coord_r = fmaf(coef_r, fj, P_r).
    __shared__ float Pre[SS][8];             // [s][{cx,Px,cy,Py,cz,Pz,_,_}]
    __shared__ float tile[32][SS + 1];       // [w_local][s]

    const int b  = blockIdx.z;
    const int h  = blockIdx.y;
    const int w0 = blockIdx.x * 32;
    const int tx = threadIdx.x;              // w lane: 0..31
    const int ty = threadIdx.y;              // 0..7
    const int tid = ty * 32 + tx;

    const float fi = (float)h;

    // 64 s * 3 axes = 192 precompute items.
    for (int it = tid; it < SS * 3; it += 256) {
        const int s = it / 3;
        const int r = it - s * 3;
        const float* t = trf + ((size_t)b * SS + s) * 12 + r * 4;
        const float a0 = t[0] + (r == 0 ? 1.0f : 0.0f);
        const float a1 = t[1] + (r == 1 ? 1.0f : 0.0f);
        const float a2 = t[2] + (r == 2 ? 1.0f : 0.0f);
        const float a3 = t[3];
        const float fz = (float)s * ST_RATIO;
        Pre[s][r * 2]     = a1;
        Pre[s][r * 2 + 1] = fmaf(a0, fi, fmaf(a2, fz, a3));
    }
    __syncthreads();

    const __half2* __restrict__ vp = vol_p_buf + (size_t)b * (HP * DP * WW);
    const float fj = (float)(w0 + tx);

    #pragma unroll
    for (int k = 0; k < 8; k++) {
        const int s = ty * 8 + k;            // all lanes in warp share s
        const float4 q  = *reinterpret_cast<const float4*>(&Pre[s][0]);
        const float2 q2 = *reinterpret_cast<const float2*>(&Pre[s][4]);

        float x = fmaf(q.x,  fj, q.y);
        float y = fmaf(q.z,  fj, q.w);
        float z = fmaf(q2.x, fj, q2.y);

        x = fminf(fmaxf(x, 0.0f), (float)(HH - 1));
        y = fminf(fmaxf(y, 0.0f), (float)(WW - 1));
        z = fminf(fmaxf(z, 0.0f), (float)(DD - 1));

        const float xf = floorf(x), yf = floorf(y), zf = floorf(z);
        const float dx = x - xf, dy = y - yf, dz = z - zf;
        const int x0 = (int)xf, y0 = (int)yf, z0 = (int)zf;

        // padded layout: idx = (x*DP + z)*W + y ; neighbors at imm offsets
        const __half2* p = vp + ((x0 * DP + z0) * WW + y0);
        const float2 f00 = __half22float2(__ldg(p));                 // (x0,z0)
        const float2 f01 = __half22float2(__ldg(p + WW));            // (x0,z1)
        const float2 f10 = __half22float2(__ldg(p + DP * WW));       // (x1,z0)
        const float2 f11 = __half22float2(__ldg(p + DP * WW + WW));  // (x1,z1)

        // y-lerp = single FMA (delta form), then z, then x
        const float c00 = fmaf(dy, f00.y, f00.x);
        const float c01 = fmaf(dy, f01.y, f01.x);
        const float c10 = fmaf(dy, f10.y, f10.x);
        const float c11 = fmaf(dy, f11.y, f11.x);
        const float c0  = fmaf(dz, c01 - c00, c00);
        const float c1  = fmaf(dz, c11 - c10, c10);
        const float r   = fmaf(dx, c1 - c0, c0);

        tile[tx][s] = r;
    }
    __syncthreads();

    // Coalesced write: consecutive tids -> consecutive s.
    float* __restrict__ ob = out + (((size_t)b * HH + h) * WW + w0) * SS;
    #pragma unroll
    for (int idx = tid; idx < 32 * SS; idx += 256) {
        const int wl = idx >> 6;
        const int s  = idx & 63;
        ob[(size_t)wl * SS + s] = tile[wl][s];
    }
}

extern "C" void kernel_launch(void* const* d_in, const int* in_sizes, int n_in,
                              void* d_out, int out_size) {
    const float* vol = (const float*)d_in[0];
    const float* trf = (const float*)d_in[1];
    float* out = (float*)d_out;

    // Launch order (d,p,m,d): puts the pack kernel at global launch index 5,
    // where ncu's "-s 5 -c 1" capture lands. Remove once pack is tuned.
    v2s_dummy_kernel<<<1, 32>>>();
    {
        dim3 block(32, 8, 1);
        dim3 grid(DD / 32, WW / 32, BB * HP);   // (3, 5, 1288)
        v2s_pack_kernel<<<grid, block>>>(vol);
    }
    {
        dim3 block(32, 8, 1);
        dim3 grid(WW / 32, HH, BB);             // (5, 160, 8)
        v2s_main_kernel<<<grid, block>>>(trf, out);
    }
    v2s_dummy_kernel<<<1, 32>>>();
}

// round 8
// speedup vs baseline: 1.1745x; 1.0464x over previous
#include <cuda_runtime.h>
#include <cuda_fp16.h>

// V2STransformer: volume-to-slice affine resample with trilinear interpolation.
// vol: [B,H,W,D] f32 (B=8,H=160,W=160,D=96), trf: [B,S,12] (S=64), out: [B,H,W,S].
//
// Pass 1: 32x32-tile transpose+pack (fully unrolled, division-free):
//         pair[b][h][d][w] = half2(v, v[w+1 clamped]-v),
//         dims [B][H+1][D+1][W] (h=H plane dups h=H-1, d=D row dups d=D-1).
//         Measured ~29us = 5.5 TB/s on 158.6 MB (near LTS ceiling).
// Pass 2: lanes = w; 4 half2 gathers per sample at immediate offsets;
//         y-lerp is a single FMA (delta form). Measured 40.2us, L1-bound.

#define BB 8
#define HH 160
#define WW 160
#define DD 96
#define SS 64
#define ST_RATIO 1.5f
#define HP (HH + 1)   // 161 padded h-planes per batch
#define DP (DD + 1)   // 97 padded d-rows per plane

// Packed pair volume: [b][h(161)][d(97)][w(160)] half2. 80 MB.
__device__ __half2 vol_p_buf[(size_t)BB * HP * DP * WW];

// ---------------------------------------------------------------------------
// Pass 1: 32x32 tiles, block (32,8). grid = (D/32, W/32, B*HP).
// ---------------------------------------------------------------------------
__global__ __launch_bounds__(256)
void v2s_pack_kernel(const float* __restrict__ vol) {
    __shared__ float tile[33][33];          // [w_local][d_local]

    const int d0 = blockIdx.x * 32;         // 0, 32, 64
    const int w0 = blockIdx.y * 32;         // 0..128
    const int bh = blockIdx.z;              // b*HP + h_padded
    const int b  = bh / HP;
    const int hh = bh - b * HP;             // 0..160
    const int hs = min(hh, HH - 1);         // plane 160 = copy of 159
    const int tx = threadIdx.x;             // 32
    const int ty = threadIdx.y;             // 8

    const float* __restrict__ src = vol + ((size_t)b * HH + hs) * WW * DD;
    __half2* __restrict__ dst = vol_p_buf + (size_t)bh * DP * WW;   // [d][w]

    // Load 32 w-rows x 32 d, coalesced along d. 4 independent LDGs/thread.
    #pragma unroll
    for (int i = 0; i < 32; i += 8)
        tile[ty + i][tx] = src[(size_t)(w0 + ty + i) * DD + d0 + tx];
    // Extra boundary row (w0+32, clamped) for the pairing neighbor.
    if (ty == 0) {
        const int wsrc = min(w0 + 32, WW - 1);
        tile[32][tx] = src[(size_t)wsrc * DD + d0 + tx];
    }
    __syncthreads();

    // Emit (v, v[w+1]-v): lanes along w (stride-33 LDS, conflict-free),
    // coalesced 4B stores. 4 unrolled iterations, constant index math.
    #pragma unroll
    for (int i = 0; i < 32; i += 8) {
        const int dl = ty + i;
        const float a = tile[tx][dl];
        const float c = tile[tx + 1][dl];
        dst[(size_t)(d0 + dl) * WW + w0 + tx] = __floats2half2_rn(a, c - a);
    }
    // d-pad row 96 (copy of d=95), emitted by the d0==64 blocks, warp 7.
    if (d0 == 64 && ty == 7) {
        const float a = tile[tx][31];
        const float c = tile[tx + 1][31];
        dst[(size_t)96 * WW + w0 + tx] = __floats2half2_rn(a, c - a);
    }
}

// ---------------------------------------------------------------------------
// Pass 2: main resample. Block = (32 w-lanes, 8), covers (1 h, 32 w, 64 s).
// ---------------------------------------------------------------------------
__global__ __launch_bounds__(256, 4)
void v2s_main_kernel(const float* __restrict__ trf,
                     float* __restrict__ out) {
    // Per-s fused affine partials: coord_r = fmaf(coef_r, fj, P_r).
    __shared__ float Pre[SS][8];             // [s][{cx,Px,cy,Py,cz,Pz,_,_}]
    __shared__ float tile[32][SS + 1];       // [w_local][s]

    const int b  = blockIdx.z;
    const int h  = blockIdx.y;
    const int w0 = blockIdx.x * 32;
    const int tx = threadIdx.x;              // w lane: 0..31
    const int ty = threadIdx.y;              // 0..7
    const int tid = ty * 32 + tx;

    const float fi = (float)h;

    // 64 s * 3 axes = 192 precompute items.
    for (int it = tid; it < SS * 3; it += 256) {
        const int s = it / 3;
        const int r = it - s * 3;
        const float* t = trf + ((size_t)b * SS + s) * 12 + r * 4;
        const float a0 = t[0] + (r == 0 ? 1.0f : 0.0f);
        const float a1 = t[1] + (r == 1 ? 1.0f : 0.0f);
        const float a2 = t[2] + (r == 2 ? 1.0f : 0.0f);
        const float a3 = t[3];
        const float fz = (float)s * ST_RATIO;
        Pre[s][r * 2]     = a1;
        Pre[s][r * 2 + 1] = fmaf(a0, fi, fmaf(a2, fz, a3));
    }
    __syncthreads();

    const __half2* __restrict__ vp = vol_p_buf + (size_t)b * (HP * DP * WW);
    const float fj = (float)(w0 + tx);

    #pragma unroll
    for (int k = 0; k < 8; k++) {
        const int s = ty * 8 + k;            // all lanes in warp share s
        const float4 q  = *reinterpret_cast<const float4*>(&Pre[s][0]);
        const float2 q2 = *reinterpret_cast<const float2*>(&Pre[s][4]);

        float x = fmaf(q.x,  fj, q.y);
        float y = fmaf(q.z,  fj, q.w);
        float z = fmaf(q2.x, fj, q2.y);

        x = fminf(fmaxf(x, 0.0f), (float)(HH - 1));
        y = fminf(fmaxf(y, 0.0f), (float)(WW - 1));
        z = fminf(fmaxf(z, 0.0f), (float)(DD - 1));

        const float xf = floorf(x), yf = floorf(y), zf = floorf(z);
        const float dx = x - xf, dy = y - yf, dz = z - zf;
        const int x0 = (int)xf, y0 = (int)yf, z0 = (int)zf;

        // padded layout: idx = (x*DP + z)*W + y ; neighbors at imm offsets
        const __half2* p = vp + ((x0 * DP + z0) * WW + y0);
        const float2 f00 = __half22float2(__ldg(p));                 // (x0,z0)
        const float2 f01 = __half22float2(__ldg(p + WW));            // (x0,z1)
        const float2 f10 = __half22float2(__ldg(p + DP * WW));       // (x1,z0)
        const float2 f11 = __half22float2(__ldg(p + DP * WW + WW));  // (x1,z1)

        // y-lerp = single FMA (delta form), then z, then x
        const float c00 = fmaf(dy, f00.y, f00.x);
        const float c01 = fmaf(dy, f01.y, f01.x);
        const float c10 = fmaf(dy, f10.y, f10.x);
        const float c11 = fmaf(dy, f11.y, f11.x);
        const float c0  = fmaf(dz, c01 - c00, c00);
        const float c1  = fmaf(dz, c11 - c10, c10);
        const float r   = fmaf(dx, c1 - c0, c0);

        tile[tx][s] = r;
    }
    __syncthreads();

    // Coalesced write: consecutive tids -> consecutive s.
    float* __restrict__ ob = out + (((size_t)b * HH + h) * WW + w0) * SS;
    #pragma unroll
    for (int idx = tid; idx < 32 * SS; idx += 256) {
        const int wl = idx >> 6;
        const int s  = idx & 63;
        ob[(size_t)wl * SS + s] = tile[wl][s];
    }
}

extern "C" void kernel_launch(void* const* d_in, const int* in_sizes, int n_in,
                              void* d_out, int out_size) {
    const float* vol = (const float*)d_in[0];
    const float* trf = (const float*)d_in[1];
    float* out = (float*)d_out;

    {
        dim3 block(32, 8, 1);
        dim3 grid(DD / 32, WW / 32, BB * HP);   // (3, 5, 1288)
        v2s_pack_kernel<<<grid, block>>>(vol);
    }
    {
        dim3 block(32, 8, 1);
        dim3 grid(WW / 32, HH, BB);             // (5, 160, 8)
        v2s_main_kernel<<<grid, block>>>(trf, out);
    }
}

// round 9
// speedup vs baseline: 1.2130x; 1.0328x over previous
#include <cuda_runtime.h>
#include <cuda_fp16.h>

// V2STransformer: volume-to-slice affine resample with trilinear interpolation.
// vol: [B,H,W,D] f32 (B=8,H=160,W=160,D=96), trf: [B,S,12] (S=64), out: [B,H,W,S].
//
// Pass 1: 32x32-tile transpose+pack (fully unrolled, division-free):
//         pair[b][h][d][w] = half2(v, v[w+1 clamped]-v), dims [B][H+1][D+1][W].
//         Measured ~29us = 5.5 TB/s (near LTS ceiling). Done.
// Pass 2: lanes = w; 4 half2 gathers/sample at immediate offsets; results
//         buffered in regs and moved via STS.128/LDS.128/STG.128 epilogue
//         (cuts non-gather l1tex wavefronts ~70%).

#define BB 8
#define HH 160
#define WW 160
#define DD 96
#define SS 64
#define ST_RATIO 1.5f
#define HP (HH + 1)   // 161 padded h-planes per batch
#define DP (DD + 1)   // 97 padded d-rows per plane
#define TSTRIDE 68    // tile row stride in floats (16B-aligned rows, conflict-free STS.128)

// Packed pair volume: [b][h(161)][d(97)][w(160)] half2. 80 MB.
__device__ __half2 vol_p_buf[(size_t)BB * HP * DP * WW];

// ---------------------------------------------------------------------------
// Pass 1: 32x32 tiles, block (32,8). grid = (D/32, W/32, B*HP).
// ---------------------------------------------------------------------------
__global__ __launch_bounds__(256)
void v2s_pack_kernel(const float* __restrict__ vol) {
    __shared__ float tile[33][33];          // [w_local][d_local]

    const int d0 = blockIdx.x * 32;         // 0, 32, 64
    const int w0 = blockIdx.y * 32;         // 0..128
    const int bh = blockIdx.z;              // b*HP + h_padded
    const int b  = bh / HP;
    const int hh = bh - b * HP;             // 0..160
    const int hs = min(hh, HH - 1);         // plane 160 = copy of 159
    const int tx = threadIdx.x;             // 32
    const int ty = threadIdx.y;             // 8

    const float* __restrict__ src = vol + ((size_t)b * HH + hs) * WW * DD;
    __half2* __restrict__ dst = vol_p_buf + (size_t)bh * DP * WW;   // [d][w]

    // Load 32 w-rows x 32 d, coalesced along d. 4 independent LDGs/thread.
    #pragma unroll
    for (int i = 0; i < 32; i += 8)
        tile[ty + i][tx] = src[(size_t)(w0 + ty + i) * DD + d0 + tx];
    // Extra boundary row (w0+32, clamped) for the pairing neighbor.
    if (ty == 0) {
        const int wsrc = min(w0 + 32, WW - 1);
        tile[32][tx] = src[(size_t)wsrc * DD + d0 + tx];
    }
    __syncthreads();

    // Emit (v, v[w+1]-v): lanes along w (stride-33 LDS, conflict-free),
    // coalesced 4B stores. 4 unrolled iterations, constant index math.
    #pragma unroll
    for (int i = 0; i < 32; i += 8) {
        const int dl = ty + i;
        const float a = tile[tx][dl];
        const float c = tile[tx + 1][dl];
        dst[(size_t)(d0 + dl) * WW + w0 + tx] = __floats2half2_rn(a, c - a);
    }
    // d-pad row 96 (copy of d=95), emitted by the d0==64 blocks, warp 7.
    if (d0 == 64 && ty == 7) {
        const float a = tile[tx][31];
        const float c = tile[tx + 1][31];
        dst[(size_t)96 * WW + w0 + tx] = __floats2half2_rn(a, c - a);
    }
}

// ---------------------------------------------------------------------------
// Pass 2: main resample. Block = (32 w-lanes, 8), covers (1 h, 32 w, 64 s).
// ---------------------------------------------------------------------------
__global__ __launch_bounds__(256, 4)
void v2s_main_kernel(const float* __restrict__ trf,
                     float* __restrict__ out) {
    // Per-s fused affine partials: coord_r = fmaf(coef_r, fj, P_r).
    __shared__ float Pre[SS][8];               // [s][{cx,Px,cy,Py,cz,Pz,_,_}]
    __shared__ float tile[32 * TSTRIDE];       // [w_local][s], stride 68

    const int b  = blockIdx.z;
    const int h  = blockIdx.y;
    const int w0 = blockIdx.x * 32;
    const int tx = threadIdx.x;              // w lane: 0..31
    const int ty = threadIdx.y;              // 0..7
    const int tid = ty * 32 + tx;

    const float fi = (float)h;

    // 64 s * 3 axes = 192 precompute items.
    for (int it = tid; it < SS * 3; it += 256) {
        const int s = it / 3;
        const int r = it - s * 3;
        const float* t = trf + ((size_t)b * SS + s) * 12 + r * 4;
        const float a0 = t[0] + (r == 0 ? 1.0f : 0.0f);
        const float a1 = t[1] + (r == 1 ? 1.0f : 0.0f);
        const float a2 = t[2] + (r == 2 ? 1.0f : 0.0f);
        const float a3 = t[3];
        const float fz = (float)s * ST_RATIO;
        Pre[s][r * 2]     = a1;
        Pre[s][r * 2 + 1] = fmaf(a0, fi, fmaf(a2, fz, a3));
    }
    __syncthreads();

    const __half2* __restrict__ vp = vol_p_buf + (size_t)b * (HP * DP * WW);
    const float fj = (float)(w0 + tx);

    float rr[8];

    #pragma unroll
    for (int k = 0; k < 8; k++) {
        const int s = ty * 8 + k;            // all lanes in warp share s
        const float4 q  = *reinterpret_cast<const float4*>(&Pre[s][0]);
        const float2 q2 = *reinterpret_cast<const float2*>(&Pre[s][4]);

        float x = fmaf(q.x,  fj, q.y);
        float y = fmaf(q.z,  fj, q.w);
        float z = fmaf(q2.x, fj, q2.y);

        x = fminf(fmaxf(x, 0.0f), (float)(HH - 1));
        y = fminf(fmaxf(y, 0.0f), (float)(WW - 1));
        z = fminf(fmaxf(z, 0.0f), (float)(DD - 1));

        const float xf = floorf(x), yf = floorf(y), zf = floorf(z);
        const float dx = x - xf, dy = y - yf, dz = z - zf;
        const int x0 = (int)xf, y0 = (int)yf, z0 = (int)zf;

        // padded layout: idx = (x*DP + z)*W + y ; neighbors at imm offsets
        const __half2* p = vp + ((x0 * DP + z0) * WW + y0);
        const float2 f00 = __half22float2(__ldg(p));                 // (x0,z0)
        const float2 f01 = __half22float2(__ldg(p + WW));            // (x0,z1)
        const float2 f10 = __half22float2(__ldg(p + DP * WW));       // (x1,z0)
        const float2 f11 = __half22float2(__ldg(p + DP * WW + WW));  // (x1,z1)

        // y-lerp = single FMA (delta form), then z, then x
        const float c00 = fmaf(dy, f00.y, f00.x);
        const float c01 = fmaf(dy, f01.y, f01.x);
        const float c10 = fmaf(dy, f10.y, f10.x);
        const float c11 = fmaf(dy, f11.y, f11.x);
        const float c0  = fmaf(dz, c01 - c00, c00);
        const float c1  = fmaf(dz, c11 - c10, c10);
        rr[k] = fmaf(dx, c1 - c0, c0);
    }

    // Two STS.128 per thread (8 consecutive s in the tile row; stride 68
    // words -> quarter-warp lanes hit 32 distinct banks: conflict-free).
    {
        float4* trow = reinterpret_cast<float4*>(&tile[tx * TSTRIDE + ty * 8]);
        trow[0] = make_float4(rr[0], rr[1], rr[2], rr[3]);
        trow[1] = make_float4(rr[4], rr[5], rr[6], rr[7]);
    }
    __syncthreads();

    // Vector epilogue: 512 float4s, 2 per thread. LDS.128 + STG.128, coalesced.
    float4* __restrict__ ob4 =
        reinterpret_cast<float4*>(out + (((size_t)b * HH + h) * WW + w0) * SS);
    #pragma unroll
    for (int it = 0; it < 2; it++) {
        const int vid = tid + it * 256;      // 0..511
        const int wl  = vid >> 4;            // 16 float4 per w-row
        const int s4  = vid & 15;
        const float4 v = *reinterpret_cast<const float4*>(&tile[wl * TSTRIDE + s4 * 4]);
        ob4[wl * (SS / 4) + s4] = v;
    }
}

extern "C" void kernel_launch(void* const* d_in, const int* in_sizes, int n_in,
                              void* d_out, int out_size) {
    const float* vol = (const float*)d_in[0];
    const float* trf = (const float*)d_in[1];
    float* out = (float*)d_out;

    {
        dim3 block(32, 8, 1);
        dim3 grid(DD / 32, WW / 32, BB * HP);   // (3, 5, 1288)
        v2s_pack_kernel<<<grid, block>>>(vol);
    }
    {
        dim3 block(32, 8, 1);
        dim3 grid(WW / 32, HH, BB);             // (5, 160, 8)
        v2s_main_kernel<<<grid, block>>>(trf, out);
    }
}